// round 8
// baseline (speedup 1.0000x reference)
#include <cuda_runtime.h>
#include <stdint.h>

#define GH 52
#define GW 52
#define NB 5
#define NBOX 13520                 // 52*52*5
#define ROWBITS 288                // padded positions per grid row (260 used)
#define PWORDS 468
#define PPOS   (PWORDS*32)         // 14976 padded positions
#define IOU_T  0.4f
#define NMS_T  1024

// Per-position masks (padded layout), 15 bits per row, bit (dx+1)*5+bb.
// g_pm: predecessors (higher priority, IoU>0.4). g_sm: successors (lower
// priority, IoU>0.4). x=dy-1, y=dy0, z=dy+1, w unused. Invalid/padding
// positions are never written and stay zero.
__device__ ushort4 g_pm[PPOS];
__device__ ushort4 g_sm[PPOS];

// ---------------------------------------------------------------------------
// Kernel 1: decode + pred/succ masks. One thread per (box, dyRow).
// Identical fp32 op sequence as the reference decode -> exact. Edge symmetry
// is exact: min/max/add are commutative, priority is a strict total order.
// ---------------------------------------------------------------------------
__global__ void decode_kernel(const float* __restrict__ x, float* __restrict__ out)
{
    int id = blockIdx.x * blockDim.x + threadIdx.x;
    if (id >= 3 * NBOX) return;
    int dyI = id / NBOX;            // 0,1,2 -> dy = dyI-1
    int j   = id - dyI * NBOX;

    int cell = j / NB;
    int b    = j - cell * NB;
    int gy   = cell / GW;
    int gx   = cell - gy * GW;

    const float sx = 416.0f / GW;   // 8
    const float sy = 416.0f / GH;   // 8

    const float* p = x + j * 5;
    float c0 = p[0], c1 = p[1], c2 = p[2], c3 = p[3], sj = p[4];

    float cx = (c0 + (float)gx) * sx;
    float w  = c2 * sx;
    float cy = (c1 + (float)gy) * sy;
    float h  = c3 * sy;
    cy = 416.0f - cy;
    float jx1 = cx - w * 0.5f, jy1 = cy - h * 0.5f;
    float jx2 = cx + w * 0.5f, jy2 = cy + h * 0.5f;

    if (dyI == 1) {
        float* o = out + j * 5;
        o[0] = jx1; o[1] = jy1; o[2] = jx2; o[3] = jy2;
        // o[4] written by nms_kernel.
    }

    float aj = fmaxf(jx2 - jx1, 0.0f) * fmaxf(jy2 - jy1, 0.0f);

    unsigned pmask = 0, smask = 0;
    int ny = gy + dyI - 1;
    if ((unsigned)ny < GH) {
        #pragma unroll
        for (int dxi = 0; dxi < 3; dxi++) {
            int nx = gx + dxi - 1;
            if ((unsigned)nx >= GW) continue;
            int ncell = ny * GW + nx;
            const float* cp = x + ncell * 25;
            float q[25];
            #pragma unroll
            for (int k = 0; k < 25; k++) q[k] = cp[k];

            #pragma unroll
            for (int bb = 0; bb < NB; bb++) {
                int i = ncell * NB + bb;
                float si = q[bb * 5 + 4];
                bool higher = (si > sj) || (si == sj && i < j);
                float d0 = q[bb * 5 + 0], d1 = q[bb * 5 + 1];
                float d2 = q[bb * 5 + 2], d3 = q[bb * 5 + 3];
                float icx = (d0 + (float)nx) * sx;
                float iw_ = d2 * sx;
                float icy = (d1 + (float)ny) * sy;
                float ih_ = d3 * sy;
                icy = 416.0f - icy;
                float ix1 = icx - iw_ * 0.5f, iy1 = icy - ih_ * 0.5f;
                float ix2 = icx + iw_ * 0.5f, iy2 = icy + ih_ * 0.5f;

                float iw = fmaxf(fminf(ix2, jx2) - fmaxf(ix1, jx1), 0.0f);
                float ih = fmaxf(fminf(iy2, jy2) - fmaxf(iy1, jy1), 0.0f);
                float inter = iw * ih;
                float ai  = fmaxf(ix2 - ix1, 0.0f) * fmaxf(iy2 - iy1, 0.0f);
                float uni = ai + aj - inter;
                float iou = (uni > 0.0f) ? inter / fmaxf(uni, 1e-12f) : 0.0f;
                bool e = (iou > IOU_T) && (i != j);
                unsigned bit = 1u << (dxi * 5 + bb);
                pmask |= (e && higher)  ? bit : 0u;
                smask |= (e && !higher) ? bit : 0u;
            }
        }
    }
    int pos = gy * ROWBITS + gx * 5 + b;
    ((unsigned short*)&g_pm[pos])[dyI] = (unsigned short)pmask;
    ((unsigned short*)&g_sm[pos])[dyI] = (unsigned short)smask;
}

// ---------------------------------------------------------------------------
// Kernel 2: work-efficient DAG peeling NMS. Single CTA, 1024 threads.
// W[pos] = (suppressCount<<16) | undecidedPredCount. Each decided pred
// issues ONE atomicAdd per edge: kept pred adds 0xFFFF (S+=1, C-=1),
// suppressed pred adds -1 (C-=1). The unique thread seeing C:1->0 decides
// the target (kept iff S_after==0) and pushes it. Level-synchronous queue;
// 2 barriers per DAG level. Exact greedy NMS, deterministic.
// ---------------------------------------------------------------------------
extern __shared__ uint8_t smraw[];

__global__ void __launch_bounds__(NMS_T, 1)
nms_kernel(const float* __restrict__ x, float* __restrict__ out)
{
    int*      W   = (int*)smraw;                         // PPOS * 4
    uint32_t* q   = (uint32_t*)(smraw + PPOS * 4);       // PPOS * 4
    uint8_t*  res = smraw + PPOS * 8;                    // PPOS * 1
    __shared__ int qtail;

    int t = threadIdx.x;
    if (t == 0) qtail = 0;
    __syncthreads();

    // Init: counters, res, and level-0 frontier (pc==0 boxes with succ).
    for (int pos = t; pos < PPOS; pos += NMS_T) {
        ushort4 pm = __ldg(&g_pm[pos]);
        ushort4 sm = __ldg(&g_sm[pos]);
        int pc = __popc(pm.x) + __popc(pm.y) + __popc(pm.z);
        W[pos] = pc;
        uint8_t r0 = 0;
        if (pc == 0) {
            r0 = 1;                                      // kept
            if (sm.x | sm.y | sm.z) {
                int rem = pos % ROWBITS;                 // sm!=0 => valid pos
                int bb  = rem % 5;
                int slot = atomicAdd(&qtail, 1);
                q[slot] = (unsigned)pos | ((unsigned)bb << 24) | 0x80000000u;
            }
        }
        res[pos] = r0;
    }

    // Level-synchronous peeling.
    int s = 0;
    while (true) {
        __syncthreads();                 // all pushes from prev level done
        int e = qtail;                   // no pushes in flight here
        __syncthreads();                 // everyone read the same e
        if (s >= e) break;

        for (int i = s + t; i < e; i += NMS_T) {
            uint32_t ent = q[i];
            int pos      = ent & 0x3FFF;
            int bb       = (ent >> 24) & 7;
            unsigned kept = ent >> 31;
            ushort4 sm = __ldg(&g_sm[pos]);
            int base = pos - bb - 5;
            unsigned delta = kept ? 0xFFFFu : 0xFFFFFFFFu;
            unsigned rows0 = sm.x, rows1 = sm.y, rows2 = sm.z;
            #pragma unroll
            for (int dy = 0; dy < 3; dy++) {
                unsigned m = (dy == 0) ? rows0 : (dy == 1) ? rows1 : rows2;
                int rbase = base + (dy - 1) * ROWBITS;
                while (m) {
                    int sb = __ffs(m) - 1; m &= m - 1;
                    int tgt = rbase + sb;
                    unsigned old = atomicAdd((unsigned*)&W[tgt], delta);
                    if ((old & 0xFFFFu) == 1u) {         // unique decider
                        unsigned sup = (old >> 16) + kept;
                        unsigned keptT = (sup == 0u) ? 1u : 0u;
                        if (keptT) res[tgt] = 1;
                        int bt = sb - (sb >= 5 ? 5 : 0);
                        bt -= (bt >= 5 ? 5 : 0);
                        int slot = atomicAdd(&qtail, 1);
                        q[slot] = (unsigned)tgt | ((unsigned)bt << 24)
                                  | (keptT << 31);
                    }
                }
            }
        }
        s = e;
    }

    // Writeout: score if kept else 0.
    for (int pos = t; pos < PPOS; pos += NMS_T) {
        int row = pos / ROWBITS;
        int rem = pos - row * ROWBITS;
        if (rem < 260) {
            int j = row * 260 + rem;
            out[j * 5 + 4] = res[pos] ? __ldg(&x[j * 5 + 4]) : 0.0f;
        }
    }
}

// ---------------------------------------------------------------------------
extern "C" void kernel_launch(void* const* d_in, const int* in_sizes, int n_in,
                              void* d_out, int out_size)
{
    const float* x   = (const float*)d_in[0];
    float*       out = (float*)d_out;

    const int smb = PPOS * 9;        // W(4) + q(4) + res(1) per position
    cudaFuncSetAttribute(nms_kernel,
                         cudaFuncAttributeMaxDynamicSharedMemorySize, smb);

    decode_kernel<<<(3 * NBOX + 255) / 256, 256>>>(x, out);
    nms_kernel<<<1, NMS_T, smb>>>(x, out);
}

// round 9
// speedup vs baseline: 2.0756x; 2.0756x over previous
#include <cuda_runtime.h>
#include <stdint.h>

#define GH 52
#define GW 52
#define NB 5
#define NBOX 13520                 // 52*52*5
#define ROWBITS 288                // padded positions per grid row (260 used)
#define PWORDS 468
#define PPOS   (PWORDS*32)         // 14976 padded positions
#define IOU_T  0.4f
#define STK    96

// Per-position predecessor masks (padded layout): x=dy-1, y=dy0, z=dy+1,
// 15 bits each (bit (dx+1)*5+bb). Padding positions never written/read.
__device__ ushort4 g_pm[PPOS];
// Memo: 0=unknown, 1=kept, 2=suppressed. Re-zeroed by decode every launch.
__device__ uint8_t g_st[PPOS];

// ---------------------------------------------------------------------------
// Kernel 1: decode + predecessor masks (proven-exact R5 version) + memo reset.
// One thread per (box, dyRow).
// ---------------------------------------------------------------------------
__global__ void decode_kernel(const float* __restrict__ x, float* __restrict__ out)
{
    int id = blockIdx.x * blockDim.x + threadIdx.x;
    if (id >= 3 * NBOX) return;
    int dyI = id / NBOX;            // 0,1,2 -> dy = dyI-1
    int j   = id - dyI * NBOX;

    int cell = j / NB;
    int b    = j - cell * NB;
    int gy   = cell / GW;
    int gx   = cell - gy * GW;

    const float sx = 416.0f / GW;   // 8
    const float sy = 416.0f / GH;   // 8

    const float* p = x + j * 5;
    float c0 = p[0], c1 = p[1], c2 = p[2], c3 = p[3], sj = p[4];

    float cx = (c0 + (float)gx) * sx;
    float w  = c2 * sx;
    float cy = (c1 + (float)gy) * sy;
    float h  = c3 * sy;
    cy = 416.0f - cy;
    float jx1 = cx - w * 0.5f, jy1 = cy - h * 0.5f;
    float jx2 = cx + w * 0.5f, jy2 = cy + h * 0.5f;

    int pos = gy * ROWBITS + gx * 5 + b;

    if (dyI == 1) {
        float* o = out + j * 5;
        o[0] = jx1; o[1] = jy1; o[2] = jx2; o[3] = jy2;
        g_st[pos] = 0;              // memo reset (graph-replay safe)
        // o[4] written by resolve_kernel.
    }

    float aj = fmaxf(jx2 - jx1, 0.0f) * fmaxf(jy2 - jy1, 0.0f);

    unsigned mask = 0;
    int ny = gy + dyI - 1;
    if ((unsigned)ny < GH) {
        #pragma unroll
        for (int dxi = 0; dxi < 3; dxi++) {
            int nx = gx + dxi - 1;
            if ((unsigned)nx >= GW) continue;
            int ncell = ny * GW + nx;
            const float* cp = x + ncell * 25;
            float q[25];
            #pragma unroll
            for (int k = 0; k < 25; k++) q[k] = cp[k];

            #pragma unroll
            for (int bb = 0; bb < NB; bb++) {
                int i = ncell * NB + bb;
                float si = q[bb * 5 + 4];
                bool higher = (si > sj) || (si == sj && i < j);
                float d0 = q[bb * 5 + 0], d1 = q[bb * 5 + 1];
                float d2 = q[bb * 5 + 2], d3 = q[bb * 5 + 3];
                float icx = (d0 + (float)nx) * sx;
                float iw_ = d2 * sx;
                float icy = (d1 + (float)ny) * sy;
                float ih_ = d3 * sy;
                icy = 416.0f - icy;
                float ix1 = icx - iw_ * 0.5f, iy1 = icy - ih_ * 0.5f;
                float ix2 = icx + iw_ * 0.5f, iy2 = icy + ih_ * 0.5f;

                float iw = fmaxf(fminf(ix2, jx2) - fmaxf(ix1, jx1), 0.0f);
                float ih = fmaxf(fminf(iy2, jy2) - fmaxf(iy1, jy1), 0.0f);
                float inter = iw * ih;
                float ai  = fmaxf(ix2 - ix1, 0.0f) * fmaxf(iy2 - iy1, 0.0f);
                float uni = ai + aj - inter;
                float iou = (uni > 0.0f) ? inter / fmaxf(uni, 1e-12f) : 0.0f;
                bool on = (iou > IOU_T) && higher && (i != j);
                mask |= (on ? 1u : 0u) << (dxi * 5 + bb);
            }
        }
    }
    ((unsigned short*)&g_pm[pos])[dyI] = (unsigned short)mask;
}

// ---------------------------------------------------------------------------
// Kernel 2: per-box memoized DFS resolution. One thread per box, no barriers.
// kept[p] = no pred q (strictly higher priority, IoU>0.4) with kept[q].
// Well-founded (priority increases along preds) => DFS terminates; result is
// the unique greedy-NMS fixpoint. Memo writes are idempotent deterministic
// values; stale reads only cause recomputation, never wrong answers.
// rem bit layout: bit (dyI*16 + q), q = dxi*5+bb; pred = pbase + (k>>4)*288
// + (k&15), pbase = framePos - bb - 288 - 5.
// ---------------------------------------------------------------------------
__global__ void __launch_bounds__(256)
resolve_kernel(const float* __restrict__ x, float* __restrict__ out)
{
    int j = blockIdx.x * blockDim.x + threadIdx.x;
    if (j >= NBOX) return;
    int row = j / 260;
    int rem = j - row * 260;
    int pos = row * ROWBITS + rem;

    volatile uint8_t* st = g_st;

    ushort4 pm = __ldg(&g_pm[pos]);
    uint64_t m0 = (uint64_t)pm.x | ((uint64_t)pm.y << 16) | ((uint64_t)pm.z << 32);

    int res;
    if (m0 == 0ull) {
        res = 1;
        st[pos] = 1;
    } else {
        int pre = st[pos];                 // someone may have resolved us
        if (pre) {
            res = pre;
        } else {
            int      fpos[STK], fpb[STK];
            uint64_t frem[STK];
            fpos[0] = pos;
            fpb[0]  = pos - (rem % 5) - ROWBITS - 5;
            frem[0] = m0;
            int sp = 1;
            res = 0;
            while (sp > 0) {
                uint64_t r = frem[sp - 1];
                int fin = 0;
                if (r == 0ull) {
                    fin = 1;                               // no kept pred -> kept
                } else {
                    int k = __ffsll((long long)r) - 1;
                    frem[sp - 1] = r & (r - 1);
                    int q    = k & 15;
                    int pred = fpb[sp - 1] + (k >> 4) * ROWBITS + q;
                    int sv = st[pred];
                    if (sv == 1) {
                        fin = 2;                           // kept pred -> suppressed
                    } else if (sv == 0) {
                        ushort4 pp = __ldg(&g_pm[pred]);
                        uint64_t m = (uint64_t)pp.x | ((uint64_t)pp.y << 16)
                                   | ((uint64_t)pp.z << 32);
                        if (m == 0ull) {
                            st[pred] = 1;
                            fin = 2;
                        } else if (sp < STK) {
                            int bb = q - (q >= 5 ? 5 : 0) - (q >= 10 ? 5 : 0);
                            fpos[sp] = pred;
                            fpb[sp]  = pred - bb - ROWBITS - 5;
                            frem[sp] = m;
                            sp++;
                        } else {
                            // Overflow fallback: pred's own thread will decide
                            // it (terminates by induction on priority rank;
                            // all 53 blocks are co-resident).
                            int v;
                            do { v = st[pred]; } while (v == 0);
                            if (v == 1) fin = 2;
                        }
                    }
                    // sv == 2: suppressed pred, keep scanning
                }
                if (fin) {
                    st[fpos[sp - 1]] = (uint8_t)fin;
                    sp--;
                    if (sp == 0) {
                        res = fin;
                    } else if (fin == 1) {                 // kept child -> parent supp
                        st[fpos[sp - 1]] = 2;
                        sp--;
                        if (sp == 0) res = 2;
                    }
                }
            }
        }
    }

    out[j * 5 + 4] = (res == 1) ? __ldg(&x[j * 5 + 4]) : 0.0f;
}

// ---------------------------------------------------------------------------
extern "C" void kernel_launch(void* const* d_in, const int* in_sizes, int n_in,
                              void* d_out, int out_size)
{
    const float* x   = (const float*)d_in[0];
    float*       out = (float*)d_out;

    decode_kernel<<<(3 * NBOX + 255) / 256, 256>>>(x, out);
    resolve_kernel<<<(NBOX + 255) / 256, 256>>>(x, out);
}